// round 13
// baseline (speedup 1.0000x reference)
#include <cuda_runtime.h>
#include <stdint.h>

// SRP map on GB300 — round 9.
//
// maps[f,g] = sum_{k!=l} x[f, k*12+l, tau0[k,l,g]], then per-frame
// zero-mean + /max. Wrapped lags in {0..7} U {504..511} -> 16 slots.
//
// R9 vs R8 (17.2us; gather ran at ~35% of issue AND crossbar — single-wave
// latency exposure; prep fold only 128 blocks, DRAM-latency-bound):
//  * NSPLIT 8->16, THREADS 256->128: grid 2048 CTAs, smem 17.4KB/CTA ->
//    ~13 CTAs/SM (52 warps) and >1 wave, filling stall gaps. Inner loop
//    (verified) unchanged.
//  * prep fold 4x parallel: 512 fold blocks (4 per frame-pair).
//  * Kept: pair folding (exact), 2 frames/CTA f32x2, cp.async staging,
//    conflict-free y[r*16+slot] LDS.64, fused last-CTA normalization.

#define KLEN    512
#define GPTS    2048
#define THREADS 128
#define NFOLD   66
#define NROWS   68
#define NENT    (NROWS * 16)        // 1088 float2 = 8704 B
#define NCHUNK  17
#define NSPLIT  16
#define MAXF2   256
#define PACK_BLOCKS (NCHUNK * 32)   // 544
#define FOLD_SPLIT 4                // fold blocks per frame pair

__constant__ uint8_t c_pairA[NFOLD] = {
  1,2,3,4,5,6,7,8,9,10,11,
  14,15,16,17,18,19,20,21,22,23,
  27,28,29,30,31,32,33,34,35,
  40,41,42,43,44,45,46,47,
  53,54,55,56,57,58,59,
  66,67,68,69,70,71,
  79,80,81,82,83,
  92,93,94,95,
  105,106,107,
  118,119,
  131};
__constant__ uint8_t c_pairB[NFOLD] = {
  12,24,36,48,60,72,84,96,108,120,132,
  25,37,49,61,73,85,97,109,121,133,
  38,50,62,74,86,98,110,122,134,
  51,63,75,87,99,111,123,135,
  64,76,88,100,112,124,136,
  77,89,101,113,125,137,
  90,102,114,126,138,
  103,115,127,139,
  116,128,140,
  129,141,
  142};

// g_tauB[c*2048+g]: 4 bytes = slot*8 (LDS.64 offset) for folded pairs 4c..4c+3.
__device__ __align__(16) uint32_t g_tauB[NCHUNK * GPTS];
// folded x table: y[f2][entry], entry = r*16+slot, value = (frame f0, f1)
__device__ __align__(16) float2 g_y[MAXF2 * NENT];
// last-arrival workspace
__device__ float ws_s[MAXF2 * 2 * NSPLIT];
__device__ float ws_m[MAXF2 * 2 * NSPLIT];
__device__ int   ws_c[MAXF2];            // zero-init; self-resetting

__device__ __forceinline__ int lag_of(int s) { return (s < 8) ? s : (s + 496); }

__device__ __forceinline__ uint32_t smem_u32(const void* p) {
    return (uint32_t)__cvta_generic_to_shared(p);
}
__device__ __forceinline__ void cp16(uint32_t dst, const void* src) {
    asm volatile("cp.async.cg.shared.global [%0], [%1], 16;\n"
                 :: "r"(dst), "l"(src) : "memory");
}

__device__ __forceinline__ float2 fold_entry(const float* xa, const float* xb, int i) {
    int r  = i >> 4;
    int sl = i & 15;
    float2 v = make_float2(0.0f, 0.0f);
    if (r < NFOLD) {
        int ra = (int)c_pairA[r] * KLEN + lag_of(sl);
        int rb = (int)c_pairB[r] * KLEN + lag_of((16 - sl) & 15);
        v.x = __ldg(&xa[ra]) + __ldg(&xa[rb]);
        v.y = __ldg(&xb[ra]) + __ldg(&xb[rb]);
    }
    return v;
}

// ---- prep: tau pack (blocks 0..543) + fold (4 blocks per frame pair) ----
__global__ void __launch_bounds__(256) prep_kernel(
    const int* __restrict__ tau0, const float* __restrict__ x)
{
    __shared__ uint8_t sm[256];
    const int tid = threadIdx.x;

    if (blockIdx.x < PACK_BLOCKS) {
        const int c  = blockIdx.x >> 5;
        const int gb = blockIdx.x & 31;
        const int j  = tid >> 6;
        const int gl = tid & 63;
        const int pr = c * 4 + j;
        uint8_t b = 0;
        if (pr < NFOLD) {
            uint32_t t = (uint32_t)__ldg(&tau0[(int)c_pairA[pr] * GPTS + gb * 64 + gl]);
            b = (uint8_t)((t & 15u) << 3);       // slot*8
        }
        sm[gl * 4 + j] = b;
        __syncthreads();
        if (tid < 64)
            g_tauB[c * GPTS + gb * 64 + tid] = ((const uint32_t*)sm)[tid];
    } else {
        const int q  = blockIdx.x - PACK_BLOCKS;
        const int f2 = q >> 2;                   // frame pair
        const int qt = q & 3;                    // quarter: 272 entries
        const float* xa = x + (size_t)(f2 * 2)     * (144 * KLEN);
        const float* xb = x + (size_t)(f2 * 2 + 1) * (144 * KLEN);
        float2* dst = g_y + f2 * NENT;
        int base = qt * 272;
        float2 v0 = fold_entry(xa, xb, base + tid);
        float2 v1 = make_float2(0.f, 0.f);
        if (tid < 16) v1 = fold_entry(xa, xb, base + 256 + tid);
        dst[base + tid] = v0;
        if (tid < 16) dst[base + 256 + tid] = v1;
    }
}

// ---------------- gather + fused normalization ----------------
// CTA: f2 = blockIdx.x>>4 (frame pair), s = blockIdx.x&15.  128 threads,
// each owns point g = s*128 + tid.
__global__ void __launch_bounds__(THREADS) srp_gather_kernel(
    const float* __restrict__ x, float* __restrict__ out)
{
    __shared__ __align__(16) float2   xsm[NENT];              // 8704 B
    __shared__ __align__(16) uint32_t stau[NCHUNK * THREADS]; // 8704 B
    __shared__ float red[4][THREADS / 32];
    __shared__ float bcast[4];
    __shared__ int   is_last;

    const int f2  = blockIdx.x >> 4;
    const int s   = blockIdx.x & 15;
    const int tid = threadIdx.x;
    const int f0  = f2 * 2;
    const int f1  = f0 + 1;

    // ---- Async-stage tau slice: stau[c*128+j] = g_tauB[c*2048 + s*128 + j] ----
    {
        const char* src_base = (const char*)g_tauB + (size_t)s * 512;
        uint32_t dst_base = smem_u32(stau);
#pragma unroll
        for (int k = 0; k < 5; k++) {
            int o = tid + k * THREADS;            // 16B-op index, 544 total
            if (o < NCHUNK * 32) {
                int c   = o >> 5;
                int off = (o & 31) * 16;
                cp16(dst_base + c * 512 + off, src_base + (size_t)c * 8192 + off);
            }
        }
    }
    // ---- Async-stage folded y table (544 x 16B) ----
    {
        const char* src = (const char*)(g_y + f2 * NENT);
        uint32_t dst = smem_u32(xsm);
#pragma unroll
        for (int k = 0; k < 5; k++) {
            int o = tid + k * THREADS;
            if (o < 544) cp16(dst + o * 16, src + o * 16);
        }
    }
    asm volatile("cp.async.commit_group;\n" ::: "memory");
    asm volatile("cp.async.wait_group 0;\n" ::: "memory");
    __syncthreads();

    const int g = s * THREADS + tid;
    const char* xbase = (const char*)xsm;

    unsigned long long a0 = 0ull, a1 = 0ull, a2 = 0ull, a3 = 0ull;
#pragma unroll
    for (int c = 0; c < NCHUNK; c++) {
        uint32_t w = stau[c * THREADS + tid];     // LDS.32, conflict-free
        const char* cb = xbase + c * 512;
        unsigned long long v0 = *(const unsigned long long*)(cb +   0 + __byte_perm(w, 0, 0x4440));
        unsigned long long v1 = *(const unsigned long long*)(cb + 128 + __byte_perm(w, 0, 0x4441));
        unsigned long long v2 = *(const unsigned long long*)(cb + 256 + __byte_perm(w, 0, 0x4442));
        unsigned long long v3 = *(const unsigned long long*)(cb + 384 + __byte_perm(w, 0, 0x4443));
        asm("add.rn.f32x2 %0, %0, %1;" : "+l"(a0) : "l"(v0));
        asm("add.rn.f32x2 %0, %0, %1;" : "+l"(a1) : "l"(v1));
        asm("add.rn.f32x2 %0, %0, %1;" : "+l"(a2) : "l"(v2));
        asm("add.rn.f32x2 %0, %0, %1;" : "+l"(a3) : "l"(v3));
    }

    float2 t0 = *(float2*)&a0, t1 = *(float2*)&a1;
    float2 t2 = *(float2*)&a2, t3 = *(float2*)&a3;
    float v0 = (t0.x + t1.x) + (t2.x + t3.x);     // frame f0, point g
    float v1 = (t0.y + t1.y) + (t2.y + t3.y);     // frame f1, point g

    float* o0 = out + (size_t)f0 * GPTS;
    float* o1 = out + (size_t)f1 * GPTS;
    o0[g] = v0;
    o1[g] = v1;

    // ---- CTA-local partial sum/max for both frames ----
    float s0 = v0, m0 = v0, s1 = v1, m1 = v1;
#pragma unroll
    for (int o = 16; o > 0; o >>= 1) {
        s0 += __shfl_xor_sync(0xFFFFFFFFu, s0, o);
        m0 = fmaxf(m0, __shfl_xor_sync(0xFFFFFFFFu, m0, o));
        s1 += __shfl_xor_sync(0xFFFFFFFFu, s1, o);
        m1 = fmaxf(m1, __shfl_xor_sync(0xFFFFFFFFu, m1, o));
    }
    int wid = tid >> 5, lane = tid & 31;
    if (lane == 0) {
        red[0][wid] = s0; red[1][wid] = m0;
        red[2][wid] = s1; red[3][wid] = m1;
    }
    __syncthreads();

    if (tid == 0) {
        float cs0 = 0.f, cm0 = -3.0e38f, cs1 = 0.f, cm1 = -3.0e38f;
#pragma unroll
        for (int wq = 0; wq < THREADS / 32; wq++) {
            cs0 += red[0][wq]; cm0 = fmaxf(cm0, red[1][wq]);
            cs1 += red[2][wq]; cm1 = fmaxf(cm1, red[3][wq]);
        }
        ws_s[(f0 * NSPLIT) + s] = cs0;  ws_m[(f0 * NSPLIT) + s] = cm0;
        ws_s[(f1 * NSPLIT) + s] = cs1;  ws_m[(f1 * NSPLIT) + s] = cm1;
        __threadfence();
        int old = atomicAdd(&ws_c[f2], 1);
        is_last = (old == NSPLIT - 1) ? 1 : 0;
    }
    __syncthreads();
    if (!is_last) return;

    // ---- Last CTA of this frame pair: normalize both frames ----
    if (tid == 0) {
        __threadfence();
        ws_c[f2] = 0;                            // reset for next graph replay
        const float EPS = 1e-12f;
#pragma unroll
        for (int fr = 0; fr < 2; fr++) {
            int f = f0 + fr;
            float tot = 0.f, mm = -3.0e38f;
#pragma unroll
            for (int k = 0; k < NSPLIT; k++) {   // fixed order: deterministic
                tot += ws_s[f * NSPLIT + k];
                mm = fmaxf(mm, ws_m[f * NSPLIT + k]);
            }
            float mean = tot * (1.0f / (float)GPTS);
            bcast[fr * 2]     = mean;
            bcast[fr * 2 + 1] = 1.0f / (mm - mean + EPS);
        }
    }
    __syncthreads();

    const float EPS = 1e-12f;
#pragma unroll
    for (int fr = 0; fr < 2; fr++) {
        float* of  = (fr == 0) ? o0 : o1;
        float mean = bcast[fr * 2];
        float inv  = bcast[fr * 2 + 1];
#pragma unroll
        for (int e = 0; e < 4; e++) {
            float4 q = *(const float4*)(of + e * 512 + tid * 4);
            q.x = (q.x - mean + EPS) * inv;
            q.y = (q.y - mean + EPS) * inv;
            q.z = (q.z - mean + EPS) * inv;
            q.w = (q.w - mean + EPS) * inv;
            *(float4*)(of + e * 512 + tid * 4) = q;
        }
    }
}

extern "C" void kernel_launch(void* const* d_in, const int* in_sizes, int n_in,
                              void* d_out, int out_size)
{
    const float* x;
    const int*   tau0;
    if (in_sizes[0] == 144 * GPTS) {
        tau0 = (const int*)d_in[0];
        x    = (const float*)d_in[1];
    } else {
        x    = (const float*)d_in[0];
        tau0 = (const int*)d_in[1];
    }

    int nframes = out_size / GPTS;      // 256
    int nf2     = nframes / 2;          // 128 frame pairs

    prep_kernel<<<PACK_BLOCKS + nf2 * FOLD_SPLIT, 256>>>(tau0, x);
    srp_gather_kernel<<<nf2 * NSPLIT, THREADS>>>(x, (float*)d_out);
}